// round 13
// baseline (speedup 1.0000x reference)
#include <cuda_runtime.h>
#include <cuda_bf16.h>

// Problem constants (fixed shapes from setup_inputs)
#define B_DIM 8
#define T_DIM 4096
#define D_DIM 1024
#define K_FFT 64
#define F_DIM (K_FFT / 2 + 1)        // 33

// Per-channel time-domain filters (irfft of sigmoid(mask)), mix_w/64 folded in.
// 1024 * 64 floats = 256 KB: written once by filt kernel, L2-hot for conv.
__device__ float g_filt[D_DIM * K_FFT];

// ---------------------------------------------------------------------------
// Kernel 1: build all filters ONCE (they depend on (d, n) only, not batch).
// Grid 64 blocks x 256 threads; block owns 16 channels; thread owns
// (channel, 4 n-values) with ILP-4 Chebyshev recurrences.
//   filt[d][n] = (mix_w[d]/64) * ( g0 + 2*sum_{f=1..31} g_f cos(pi f n/32)
//                                  + g32 * (-1)^n ),  g = sigmoid(mask[d])
// ---------------------------------------------------------------------------
__global__ void __launch_bounds__(256, 1) spectral_filt_kernel(
    const float* __restrict__ mask, const float* __restrict__ mix_w)
{
    __shared__ float gs_sh[16 * F_DIM];   // weighted sigmoid tile
    __shared__ float mw_sh[16];
    __shared__ float tab[K_FFT];          // a[n] = cos(pi n / 32)

    const int tid = threadIdx.x;
    const int c0  = blockIdx.x * 16;      // channel tile base

    const float* mrow = mask + (long long)c0 * F_DIM;
    for (int idx = tid; idx < 16 * F_DIM; idx += 256) {
        int f = idx % F_DIM;
        float g = 1.0f / (1.0f + __expf(-mrow[idx]));
        gs_sh[idx] = (f == 0 || f == 32) ? g : (2.0f * g);
    }
    if (tid < K_FFT)
        tab[tid] = cospif((float)tid * (1.0f / 32.0f));   // exact twiddles
    if (tid < 16)
        mw_sh[tid] = mix_w[c0 + tid] * (1.0f / 64.0f);
    __syncthreads();

    const int c  = tid >> 4;              // local channel 0..15
    const int n0 = (tid & 15) * 4;        // 4 consecutive n-values
    const float* gd = gs_sh + c * F_DIM;  // warp-broadcast-friendly reads

    float a2[4], cc[4], cp[4], s[4];
    const float g0 = gd[0];
    #pragma unroll
    for (int i = 0; i < 4; i++) {
        float a = tab[n0 + i];
        a2[i] = a + a; cp[i] = 1.0f; cc[i] = a; s[i] = g0;
    }
    #pragma unroll
    for (int f = 1; f < 32; f++) {
        const float gf = gd[f];
        #pragma unroll
        for (int i = 0; i < 4; i++) {
            s[i] = fmaf(gf, cc[i], s[i]);
            float cn = fmaf(a2[i], cc[i], -cp[i]);
            cp[i] = cc[i]; cc[i] = cn;
        }
    }
    const float g32 = gd[32];
    const float mw  = mw_sh[c];
    float* frow = g_filt + (long long)(c0 + c) * K_FFT + n0;
    #pragma unroll
    for (int i = 0; i < 4; i++)
        frow[i] = fmaf(g32, cc[i], s[i]) * mw;
}

// ---------------------------------------------------------------------------
// Kernel 2: circular convolution, build-free and wide.
// Grid 512 = (b:8) x (dtile:16) x (tq:4); block 256 threads.
// Thread owns (channel dl, 4 timesteps); fr[64] register rotation keeps the
// 64x4 inner loop at pure compile-time-indexed FFMA.
// ---------------------------------------------------------------------------
__global__ void __launch_bounds__(256, 2) spectral_conv_kernel(
    const float* __restrict__ x, float* __restrict__ out)
{
    __shared__ float w_sh[K_FFT * 64];        // window [k][dl]
    __shared__ float f_sh[64 * (K_FFT + 1)];  // filter [dl][n], pad 65

    const int bid = blockIdx.x;
    const int tid = threadIdx.x;

    const int b  = bid >> 6;            // 0..7
    const int dt = (bid >> 2) & 15;     // d-tile 0..15
    const int tq = bid & 3;             // time quarter 0..3
    const int d0 = dt * 64;

    // Stage window (coalesced) and filter tile (coalesced, L2-hot).
    const float* xb = x + ((long long)b * T_DIM + (T_DIM - K_FFT)) * D_DIM + d0;
    const float* fg = g_filt + (long long)d0 * K_FFT;
    #pragma unroll
    for (int i = 0; i < 16; i++) {
        int idx = tid + i * 256;
        int k = idx >> 6, dl = idx & 63;
        w_sh[idx] = xb[(long long)k * D_DIM + dl];
        f_sh[(idx >> 6) * 65 + (idx & 63)] = fg[idx];   // [dl][n] from row-major
    }
    __syncthreads();

    const int dl = tid & 63;
    const int t0 = tq * 16 + (tid >> 6) * 4;   // 4 outputs per thread

    // Pre-rotated filter in registers: fr[i] = f[(t0+i)&63]
    //   -> y[t0+j] = sum_k w[k] * fr[(j-k)&63], compile-time reg indices.
    float fr[K_FFT];
    #pragma unroll
    for (int i = 0; i < K_FFT; i++)
        fr[i] = f_sh[dl * 65 + ((t0 + i) & 63)];

    float acc[4];
    #pragma unroll
    for (int j = 0; j < 4; j++) acc[j] = 0.0f;

    #pragma unroll
    for (int kc = 0; kc < K_FFT; kc += 8) {
        float wbuf[8];
        #pragma unroll
        for (int u = 0; u < 8; u++)
            wbuf[u] = w_sh[(kc + u) * 64 + dl];
        #pragma unroll
        for (int u = 0; u < 8; u++) {
            const int k = kc + u;
            #pragma unroll
            for (int j = 0; j < 4; j++)
                acc[j] += wbuf[u] * fr[(j - k + K_FFT) & 63];
        }
    }

    float* ob = out + ((long long)b * T_DIM + (T_DIM - K_FFT)) * D_DIM + d0;
    #pragma unroll
    for (int j = 0; j < 4; j++)
        ob[(long long)(t0 + j) * D_DIM + dl] = acc[j];
}

// ---------------------------------------------------------------------------
// Launch: memset node (~7 TB/s driver fill) -> filt -> conv. Three graph nodes.
// filt runs after the memset so its 256 KB output stays L2-hot for conv.
// ---------------------------------------------------------------------------
extern "C" void kernel_launch(void* const* d_in, const int* in_sizes, int n_in,
                              void* d_out, int out_size)
{
    const float* x     = (const float*)d_in[0];   // (B, T, D) fp32
    const float* mask  = (const float*)d_in[1];   // (D, 33)   fp32
    const float* mix_w = (const float*)d_in[2];   // (D,)      fp32
    float* out = (float*)d_out;                   // (B, T, D) fp32

    cudaMemsetAsync(out, 0, (size_t)out_size * sizeof(float), 0);
    spectral_filt_kernel<<<64, 256>>>(mask, mix_w);
    spectral_conv_kernel<<<512, 256>>>(x, out);
}